// round 12
// baseline (speedup 1.0000x reference)
#include <cuda_runtime.h>

// out[n,m,:4] = relu( zw4[n] + xwb4[m] ),  zw4 = z@W1, xwb4 = x^T@W2 + b
// N=8192, M=128, DZ=DX=128, H=4.
//
// ONE kernel, 256 blocks x 512 threads, 32 rows/block => 2 CTAs/SM resident
// (phase overlap across CTAs is the point; R11 had 1 CTA/SM and 80% stall).
//  - warp computes zw for its OWN 2 rows; XOR-butterfly leaves the full sum
//    in every lane -> stream straight from registers, no sZW table
//  - xwb: 16-warp d-split (8 d each, 128 FFMA/thread), folded once, 2 KB table
//  - stream: 4 LDS.128 (xwb regs) then 8 coalesced STG.128 per thread

#define N_ROWS   8192
#define M_COLS   128
#define D_Z      128
#define D_X      128
#define NBLOCKS  256
#define NTHREADS 512
#define NWARPS   (NTHREADS / 32)       // 16
#define ROWS_PB  (N_ROWS / NBLOCKS)    // 32: warp owns 2 rows

__global__ __launch_bounds__(NTHREADS)
void fused_kernel(const float* __restrict__ z,
                  const float* __restrict__ x,
                  const float* __restrict__ W,
                  const float* __restrict__ b,
                  float4* __restrict__ out4)
{
    __shared__ float4 sPart[NWARPS][M_COLS];   // 32 KB xwb partials
    __shared__ float4 sXWB[M_COLS];            // 2 KB

    const int tid  = threadIdx.x;
    const int bid  = blockIdx.x;
    const int lane = tid & 31;
    const int warp = tid >> 5;                 // 0..15
    const float4* W4 = reinterpret_cast<const float4*>(W);
    const float4* x4 = reinterpret_cast<const float4*>(x);

    // ---- 1) Issue this warp's 2 z-row loads early (DRAM, MLP=2) ----
    const int n0 = bid * ROWS_PB + warp * 2;
    float4 zv0 = reinterpret_cast<const float4*>(z + (size_t)(n0 + 0) * D_Z)[lane];
    float4 zv1 = reinterpret_cast<const float4*>(z + (size_t)(n0 + 1) * D_Z)[lane];

    // ---- 2) xwb partials while z is in flight.
    //      Warp w owns d in [8w, 8w+8); lane covers m = 4*lane..4*lane+3. ----
    {
        float4 acc[4] = {{0,0,0,0},{0,0,0,0},{0,0,0,0},{0,0,0,0}};
        const int d0 = warp * 8;
        #pragma unroll
        for (int i = 0; i < 8; ++i) {
            const int d = d0 + i;
            const float4 xv = x4[d * 32 + lane];             // L2-resident
            const float4 w  = W4[D_Z + d];                   // L1 broadcast
            acc[0].x = fmaf(xv.x, w.x, acc[0].x); acc[0].y = fmaf(xv.x, w.y, acc[0].y);
            acc[0].z = fmaf(xv.x, w.z, acc[0].z); acc[0].w = fmaf(xv.x, w.w, acc[0].w);
            acc[1].x = fmaf(xv.y, w.x, acc[1].x); acc[1].y = fmaf(xv.y, w.y, acc[1].y);
            acc[1].z = fmaf(xv.y, w.z, acc[1].z); acc[1].w = fmaf(xv.y, w.w, acc[1].w);
            acc[2].x = fmaf(xv.z, w.x, acc[2].x); acc[2].y = fmaf(xv.z, w.y, acc[2].y);
            acc[2].z = fmaf(xv.z, w.z, acc[2].z); acc[2].w = fmaf(xv.z, w.w, acc[2].w);
            acc[3].x = fmaf(xv.w, w.x, acc[3].x); acc[3].y = fmaf(xv.w, w.y, acc[3].y);
            acc[3].z = fmaf(xv.w, w.z, acc[3].z); acc[3].w = fmaf(xv.w, w.w, acc[3].w);
        }
        #pragma unroll
        for (int c = 0; c < 4; ++c) sPart[warp][lane * 4 + c] = acc[c];
    }

    // ---- 3) zw for this warp's 2 rows; butterfly leaves sum in ALL lanes ----
    float4 a0, a1;
    {
        const float4 w0 = W4[lane * 4 + 0];
        const float4 w1 = W4[lane * 4 + 1];
        const float4 w2 = W4[lane * 4 + 2];
        const float4 w3 = W4[lane * 4 + 3];

        float4 t0, t1;
        t0.x = zv0.x * w0.x; t0.y = zv0.x * w0.y; t0.z = zv0.x * w0.z; t0.w = zv0.x * w0.w;
        t0.x = fmaf(zv0.y, w1.x, t0.x); t0.y = fmaf(zv0.y, w1.y, t0.y);
        t0.z = fmaf(zv0.y, w1.z, t0.z); t0.w = fmaf(zv0.y, w1.w, t0.w);
        t0.x = fmaf(zv0.z, w2.x, t0.x); t0.y = fmaf(zv0.z, w2.y, t0.y);
        t0.z = fmaf(zv0.z, w2.z, t0.z); t0.w = fmaf(zv0.z, w2.w, t0.w);
        t0.x = fmaf(zv0.w, w3.x, t0.x); t0.y = fmaf(zv0.w, w3.y, t0.y);
        t0.z = fmaf(zv0.w, w3.z, t0.z); t0.w = fmaf(zv0.w, w3.w, t0.w);

        t1.x = zv1.x * w0.x; t1.y = zv1.x * w0.y; t1.z = zv1.x * w0.z; t1.w = zv1.x * w0.w;
        t1.x = fmaf(zv1.y, w1.x, t1.x); t1.y = fmaf(zv1.y, w1.y, t1.y);
        t1.z = fmaf(zv1.y, w1.z, t1.z); t1.w = fmaf(zv1.y, w1.w, t1.w);
        t1.x = fmaf(zv1.z, w2.x, t1.x); t1.y = fmaf(zv1.z, w2.y, t1.y);
        t1.z = fmaf(zv1.z, w2.z, t1.z); t1.w = fmaf(zv1.z, w2.w, t1.w);
        t1.x = fmaf(zv1.w, w3.x, t1.x); t1.y = fmaf(zv1.w, w3.y, t1.y);
        t1.z = fmaf(zv1.w, w3.z, t1.z); t1.w = fmaf(zv1.w, w3.w, t1.w);

        #pragma unroll
        for (int off = 16; off; off >>= 1) {   // 8 independent chains: ILP
            t0.x += __shfl_xor_sync(0xffffffffu, t0.x, off);
            t0.y += __shfl_xor_sync(0xffffffffu, t0.y, off);
            t0.z += __shfl_xor_sync(0xffffffffu, t0.z, off);
            t0.w += __shfl_xor_sync(0xffffffffu, t0.w, off);
            t1.x += __shfl_xor_sync(0xffffffffu, t1.x, off);
            t1.y += __shfl_xor_sync(0xffffffffu, t1.y, off);
            t1.z += __shfl_xor_sync(0xffffffffu, t1.z, off);
            t1.w += __shfl_xor_sync(0xffffffffu, t1.w, off);
        }
        a0 = t0; a1 = t1;                      // full sums in every lane
    }
    __syncthreads();

    // ---- 4) Fold xwb partials: 128 threads, 16-way add + bias ----
    if (tid < M_COLS) {
        float4 s = *reinterpret_cast<const float4*>(b);
        #pragma unroll
        for (int w = 0; w < NWARPS; ++w) {
            const float4 p = sPart[w][tid];
            s.x += p.x; s.y += p.y; s.z += p.z; s.w += p.w;
        }
        sXWB[tid] = s;
    }
    __syncthreads();

    // ---- 5) Stream this warp's 2 rows straight from registers ----
    const float4 c0 = sXWB[lane];
    const float4 c1 = sXWB[lane + 32];
    const float4 c2 = sXWB[lane + 64];
    const float4 c3 = sXWB[lane + 96];

    float4* __restrict__ o = out4 + ((size_t)n0 << 7);   // n0 * 128

    #define EMIT(AR, ROW, CV, MOFF)                                 \
    {                                                               \
        float4 r;                                                   \
        r.x = fmaxf(AR.x + CV.x, 0.f);                              \
        r.y = fmaxf(AR.y + CV.y, 0.f);                              \
        r.z = fmaxf(AR.z + CV.z, 0.f);                              \
        r.w = fmaxf(AR.w + CV.w, 0.f);                              \
        o[(ROW << 7) + MOFF + lane] = r;                            \
    }
    EMIT(a0, 0, c0,  0) EMIT(a0, 0, c1, 32) EMIT(a0, 0, c2, 64) EMIT(a0, 0, c3, 96)
    EMIT(a1, 1, c0,  0) EMIT(a1, 1, c1, 32) EMIT(a1, 1, c2, 64) EMIT(a1, 1, c3, 96)
    #undef EMIT
}

extern "C" void kernel_launch(void* const* d_in, const int* in_sizes, int n_in,
                              void* d_out, int out_size)
{
    const float* z = (const float*)d_in[0];   // [8192,128]
    const float* x = (const float*)d_in[1];   // [128,128]
    const float* W = (const float*)d_in[2];   // [256,4]
    const float* b = (const float*)d_in[3];   // [4]
    float4* out4   = (float4*)d_out;

    fused_kernel<<<NBLOCKS, NTHREADS>>>(z, x, W, b, out4);
}

// round 13
// speedup vs baseline: 1.2149x; 1.2149x over previous
#include <cuda_runtime.h>

// out[n,m,:4] = relu( zw4[n] + xwb4[m] ),  zw4 = z@W1, xwb4 = x^T@W2 + b
// N=8192, M=128, DZ=DX=128, H=4.
//
// ONE kernel, 148 blocks (full chip, exactly one wave) x 512 threads.
// Block bid owns rows [bid*N/148, (bid+1)*N/148) = 55 or 56 rows.
// Warp owns 4 consecutive rows (16 warps x 4 = 64 >= 56; tail predicated).
//  - z loads for all 4 rows issued first (MLP=4, DRAM)
//  - xwb: 16-warp d-split (8 d each, 128 FFMA/thread) overlaps z latency;
//    chip-wide redundancy at 148 blocks ~ 0.5us (the calibrated ceiling)
//  - zw: full-lane XOR butterfly -> row sums live in every lane, stream
//    goes straight from registers (no sZW table)
//  - stream: 4 LDS.128 once, then 16 predicated coalesced STG.128

#define N_ROWS   8192
#define M_COLS   128
#define D_Z      128
#define D_X      128
#define NBLOCKS  148
#define NTHREADS 512
#define NWARPS   (NTHREADS / 32)       // 16

__global__ __launch_bounds__(NTHREADS)
void fused_kernel(const float* __restrict__ z,
                  const float* __restrict__ x,
                  const float* __restrict__ W,
                  const float* __restrict__ b,
                  float4* __restrict__ out4)
{
    __shared__ float4 sPart[NWARPS][M_COLS];   // 32 KB xwb partials
    __shared__ float4 sXWB[M_COLS];            // 2 KB

    const int tid  = threadIdx.x;
    const int bid  = blockIdx.x;
    const int lane = tid & 31;
    const int warp = tid >> 5;                 // 0..15
    const float4* W4 = reinterpret_cast<const float4*>(W);
    const float4* x4 = reinterpret_cast<const float4*>(x);

    // Row range for this block (55 or 56 rows), 4 consecutive rows per warp.
    const int r0 = (bid * N_ROWS) / NBLOCKS;
    const int r1 = ((bid + 1) * N_ROWS) / NBLOCKS;
    const int base_row = r0 + warp * 4;

    // ---- 1) Issue z loads for this warp's (up to) 4 rows first ----
    int   rown[4];
    bool  valid[4];
    float4 zv[4];
    #pragma unroll
    for (int j = 0; j < 4; ++j) {
        rown[j]  = base_row + j;
        valid[j] = rown[j] < r1;
        const int safe = valid[j] ? rown[j] : (r1 - 1);   // clamp: in-bounds, unused
        zv[j] = reinterpret_cast<const float4*>(z + (size_t)safe * D_Z)[lane];
    }

    // ---- 2) xwb partials while z is in flight.
    //      Warp w owns d in [8w, 8w+8); lane covers m = 4*lane..4*lane+3. ----
    {
        float4 acc[4] = {{0,0,0,0},{0,0,0,0},{0,0,0,0},{0,0,0,0}};
        const int d0 = warp * 8;
        #pragma unroll
        for (int i = 0; i < 8; ++i) {
            const int d = d0 + i;
            const float4 xv = x4[d * 32 + lane];             // L2-resident
            const float4 w  = W4[D_Z + d];                   // L1 broadcast
            acc[0].x = fmaf(xv.x, w.x, acc[0].x); acc[0].y = fmaf(xv.x, w.y, acc[0].y);
            acc[0].z = fmaf(xv.x, w.z, acc[0].z); acc[0].w = fmaf(xv.x, w.w, acc[0].w);
            acc[1].x = fmaf(xv.y, w.x, acc[1].x); acc[1].y = fmaf(xv.y, w.y, acc[1].y);
            acc[1].z = fmaf(xv.y, w.z, acc[1].z); acc[1].w = fmaf(xv.y, w.w, acc[1].w);
            acc[2].x = fmaf(xv.z, w.x, acc[2].x); acc[2].y = fmaf(xv.z, w.y, acc[2].y);
            acc[2].z = fmaf(xv.z, w.z, acc[2].z); acc[2].w = fmaf(xv.z, w.w, acc[2].w);
            acc[3].x = fmaf(xv.w, w.x, acc[3].x); acc[3].y = fmaf(xv.w, w.y, acc[3].y);
            acc[3].z = fmaf(xv.w, w.z, acc[3].z); acc[3].w = fmaf(xv.w, w.w, acc[3].w);
        }
        #pragma unroll
        for (int c = 0; c < 4; ++c) sPart[warp][lane * 4 + c] = acc[c];
    }

    // ---- 3) zw for 4 rows; full butterfly leaves sums in ALL lanes ----
    float4 a[4];
    {
        const float4 w0 = W4[lane * 4 + 0];
        const float4 w1 = W4[lane * 4 + 1];
        const float4 w2 = W4[lane * 4 + 2];
        const float4 w3 = W4[lane * 4 + 3];

        #pragma unroll
        for (int j = 0; j < 4; ++j) {
            float4 t;
            t.x = zv[j].x * w0.x; t.y = zv[j].x * w0.y;
            t.z = zv[j].x * w0.z; t.w = zv[j].x * w0.w;
            t.x = fmaf(zv[j].y, w1.x, t.x); t.y = fmaf(zv[j].y, w1.y, t.y);
            t.z = fmaf(zv[j].y, w1.z, t.z); t.w = fmaf(zv[j].y, w1.w, t.w);
            t.x = fmaf(zv[j].z, w2.x, t.x); t.y = fmaf(zv[j].z, w2.y, t.y);
            t.z = fmaf(zv[j].z, w2.z, t.z); t.w = fmaf(zv[j].z, w2.w, t.w);
            t.x = fmaf(zv[j].w, w3.x, t.x); t.y = fmaf(zv[j].w, w3.y, t.y);
            t.z = fmaf(zv[j].w, w3.z, t.z); t.w = fmaf(zv[j].w, w3.w, t.w);
            a[j] = t;
        }
        #pragma unroll
        for (int off = 16; off; off >>= 1) {   // 16 independent chains: ILP
            #pragma unroll
            for (int j = 0; j < 4; ++j) {
                a[j].x += __shfl_xor_sync(0xffffffffu, a[j].x, off);
                a[j].y += __shfl_xor_sync(0xffffffffu, a[j].y, off);
                a[j].z += __shfl_xor_sync(0xffffffffu, a[j].z, off);
                a[j].w += __shfl_xor_sync(0xffffffffu, a[j].w, off);
            }
        }
    }
    __syncthreads();

    // ---- 4) Fold xwb partials: 128 threads, 16-way add + bias ----
    if (tid < M_COLS) {
        float4 s = *reinterpret_cast<const float4*>(b);
        #pragma unroll
        for (int w = 0; w < NWARPS; ++w) {
            const float4 p = sPart[w][tid];
            s.x += p.x; s.y += p.y; s.z += p.z; s.w += p.w;
        }
        sXWB[tid] = s;
    }
    __syncthreads();

    // ---- 5) Stream straight from registers: up to 16 STG.128/thread ----
    const float4 c0 = sXWB[lane];
    const float4 c1 = sXWB[lane + 32];
    const float4 c2 = sXWB[lane + 64];
    const float4 c3 = sXWB[lane + 96];

    #pragma unroll
    for (int j = 0; j < 4; ++j) {
        if (valid[j]) {
            float4* __restrict__ o = out4 + ((size_t)rown[j] << 7);  // row*128
            float4 r;
            r.x = fmaxf(a[j].x + c0.x, 0.f); r.y = fmaxf(a[j].y + c0.y, 0.f);
            r.z = fmaxf(a[j].z + c0.z, 0.f); r.w = fmaxf(a[j].w + c0.w, 0.f);
            o[lane] = r;
            r.x = fmaxf(a[j].x + c1.x, 0.f); r.y = fmaxf(a[j].y + c1.y, 0.f);
            r.z = fmaxf(a[j].z + c1.z, 0.f); r.w = fmaxf(a[j].w + c1.w, 0.f);
            o[lane + 32] = r;
            r.x = fmaxf(a[j].x + c2.x, 0.f); r.y = fmaxf(a[j].y + c2.y, 0.f);
            r.z = fmaxf(a[j].z + c2.z, 0.f); r.w = fmaxf(a[j].w + c2.w, 0.f);
            o[lane + 64] = r;
            r.x = fmaxf(a[j].x + c3.x, 0.f); r.y = fmaxf(a[j].y + c3.y, 0.f);
            r.z = fmaxf(a[j].z + c3.z, 0.f); r.w = fmaxf(a[j].w + c3.w, 0.f);
            o[lane + 96] = r;
        }
    }
}

extern "C" void kernel_launch(void* const* d_in, const int* in_sizes, int n_in,
                              void* d_out, int out_size)
{
    const float* z = (const float*)d_in[0];   // [8192,128]
    const float* x = (const float*)d_in[1];   // [128,128]
    const float* W = (const float*)d_in[2];   // [256,4]
    const float* b = (const float*)d_in[3];   // [4]
    float4* out4   = (float4*)d_out;

    fused_kernel<<<NBLOCKS, NTHREADS>>>(z, x, W, b, out4);
}